// round 1
// baseline (speedup 1.0000x reference)
#include <cuda_runtime.h>
#include <math.h>

#define NTOK 4096
#define NH   16
#define HD   128
#define TXT  3072
#define SCALE 0.088388347648318447f  /* 128^-0.5 */

#define BR 64
#define BC 64
#define KSTR 130   /* smem row stride (floats) for Q/K/V tiles: pad 2 -> conflict-free, 8B aligned */
#define PSTR 66    /* smem row stride for P tile */
#define ATHREADS 256

typedef unsigned long long ull;

/* scratch: Q,K,V in [head][token][dim] layout (fp32) */
__device__ float Qg[(size_t)NH * NTOK * HD];
__device__ float Kg[(size_t)NH * NTOK * HD];
__device__ float Vg[(size_t)NH * NTOK * HD];

__device__ __forceinline__ ull pack2(float x, float y) {
    ull r; asm("mov.b64 %0, {%1,%2};" : "=l"(r) : "f"(x), "f"(y)); return r;
}
__device__ __forceinline__ void unpack2(ull v, float& x, float& y) {
    asm("mov.b64 {%0,%1}, %2;" : "=f"(x), "=f"(y) : "l"(v));
}
__device__ __forceinline__ ull ffma2(ull a, ull b, ull c) {
    ull d; asm("fma.rn.f32x2 %0, %1, %2, %3;" : "=l"(d) : "l"(a), "l"(b), "l"(c)); return d;
}
__device__ __forceinline__ ull fmul2(ull a, ull b) {
    ull d; asm("mul.rn.f32x2 %0, %1, %2;" : "=l"(d) : "l"(a), "l"(b)); return d;
}

/* ------------------------------------------------------------------ */
/* prep: qkv split + rmsnorm(q,k) + rope(q,k) + copy v                 */
/* grid: NTOK blocks, block (64,16): tx = rope pair, ty = head         */
/* ------------------------------------------------------------------ */
__global__ void prep_kernel(const float* __restrict__ x,
                            const float* __restrict__ qw,
                            const float* __restrict__ kw,
                            const float* __restrict__ f1,
                            const float* __restrict__ f2)
{
    const int n = blockIdx.x;
    const int h = threadIdx.y;
    const int i = threadIdx.x;   /* pair index 0..63 */

    const float* base = x + (size_t)n * (3 * NH * HD) + h * HD + 2 * i;
    float2 q2 = *(const float2*)(base);
    float2 k2 = *(const float2*)(base + NH * HD);
    float2 v2 = *(const float2*)(base + 2 * NH * HD);

    float sq = q2.x * q2.x + q2.y * q2.y;
    float sk = k2.x * k2.x + k2.y * k2.y;
#pragma unroll
    for (int m = 16; m >= 1; m >>= 1) {
        sq += __shfl_xor_sync(0xffffffffu, sq, m);
        sk += __shfl_xor_sync(0xffffffffu, sk, m);
    }
    __shared__ float red[NH][2][2];
    if ((i & 31) == 0) { red[h][i >> 5][0] = sq; red[h][i >> 5][1] = sk; }
    __syncthreads();
    sq = red[h][0][0] + red[h][1][0];
    sk = red[h][0][1] + red[h][1][1];

    const float rq = rsqrtf(sq * (1.0f / 128.0f) + 1e-5f);
    const float rk = rsqrtf(sk * (1.0f / 128.0f) + 1e-5f);
    float2 wq = *(const float2*)(qw + 2 * i);
    float2 wk = *(const float2*)(kw + 2 * i);
    float qx = q2.x * rq * wq.x, qy = q2.y * rq * wq.y;
    float kx = k2.x * rk * wk.x, ky = k2.y * rk * wk.y;

    float th = (n < TXT) ? f1[n * 64 + i] : f2[(n - TXT) * 64 + i];
    float sn, cs;
    sincosf(th, &sn, &cs);

    float2 qo = make_float2(qx * cs - qy * sn, qx * sn + qy * cs);
    float2 ko = make_float2(kx * cs - ky * sn, kx * sn + ky * cs);

    size_t off = ((size_t)h * NTOK + n) * HD + 2 * i;
    *(float2*)(Qg + off) = qo;
    *(float2*)(Kg + off) = ko;
    *(float2*)(Vg + off) = v2;
}

/* ------------------------------------------------------------------ */
/* flash attention, fp32, FFMA2 inner loops                            */
/* grid: (N/BR, NH), 256 threads. Thread t: row-group tr=t>>4 owns     */
/* rows r0..r0+3 in BOTH gemm phases (m/l/rescale in registers).       */
/* ------------------------------------------------------------------ */
__global__ void __launch_bounds__(ATHREADS, 1)
attn_kernel(float* __restrict__ out)
{
    extern __shared__ float sm[];
    float* Qs = sm;                    /* BR * KSTR */
    float* Ks = Qs + BR * KSTR;        /* BC * KSTR */
    float* Vs = Ks + BC * KSTR;        /* BC * KSTR */
    float* Ps = Vs + BC * KSTR;        /* BR * PSTR */

    const int h = blockIdx.y;
    const int qt = blockIdx.x;
    const int t = threadIdx.x;
    const int qbase = qt * BR;

    const float* Qh = Qg + ((size_t)h * NTOK + qbase) * HD;
    const float* Kh = Kg + (size_t)h * NTOK * HD;
    const float* Vh = Vg + (size_t)h * NTOK * HD;

    /* load Q tile (64 x 128) */
#pragma unroll
    for (int u = 0; u < 8; ++u) {
        int idx = t + u * ATHREADS;          /* 0..2047: 64 rows x 32 float4 */
        int r = idx >> 5, c4 = (idx & 31) << 2;
        float4 v = *(const float4*)(Qh + r * HD + c4);
        float* d = Qs + r * KSTR + c4;
        *(float2*)(d)     = make_float2(v.x, v.y);
        *(float2*)(d + 2) = make_float2(v.z, v.w);
    }

    const int tr = t >> 4;     /* 0..15 */
    const int tc = t & 15;     /* 0..15 */
    const int r0 = tr * 4;

    ull o2[4][4];
    float mreg[4], lreg[4];
#pragma unroll
    for (int i = 0; i < 4; ++i) {
        mreg[i] = __int_as_float(0xff800000); /* -inf */
        lreg[i] = 0.f;
#pragma unroll
        for (int m = 0; m < 4; ++m) o2[i][m] = 0ull;
    }

    for (int kt = 0; kt < NTOK / BC; ++kt) {
        __syncthreads();   /* previous iter done with Ks/Vs/Ps */
        const float* Kt = Kh + (size_t)kt * BC * HD;
        const float* Vt = Vh + (size_t)kt * BC * HD;
#pragma unroll
        for (int u = 0; u < 8; ++u) {
            int idx = t + u * ATHREADS;
            int r = idx >> 5, c4 = (idx & 31) << 2;
            float4 kv = *(const float4*)(Kt + r * HD + c4);
            float4 vv = *(const float4*)(Vt + r * HD + c4);
            float* dk = Ks + r * KSTR + c4;
            float* dv = Vs + r * KSTR + c4;
            *(float2*)(dk)     = make_float2(kv.x, kv.y);
            *(float2*)(dk + 2) = make_float2(kv.z, kv.w);
            *(float2*)(dv)     = make_float2(vv.x, vv.y);
            *(float2*)(dv + 2) = make_float2(vv.z, vv.w);
        }
        __syncthreads();

        /* S = Q K^T : rows r0+i, cols tc+16j (conflict-free K loads) */
        ull acc[4][4];
#pragma unroll
        for (int i = 0; i < 4; ++i)
#pragma unroll
            for (int j = 0; j < 4; ++j) acc[i][j] = 0ull;

#pragma unroll 4
        for (int d = 0; d < HD; d += 2) {
            ull qa[4], kb[4];
#pragma unroll
            for (int i = 0; i < 4; ++i) qa[i] = *(const ull*)(Qs + (r0 + i) * KSTR + d);
#pragma unroll
            for (int j = 0; j < 4; ++j) kb[j] = *(const ull*)(Ks + (tc + 16 * j) * KSTR + d);
#pragma unroll
            for (int i = 0; i < 4; ++i)
#pragma unroll
                for (int j = 0; j < 4; ++j)
                    acc[i][j] = ffma2(qa[i], kb[j], acc[i][j]);
        }

        float sv[4][4];
#pragma unroll
        for (int i = 0; i < 4; ++i)
#pragma unroll
            for (int j = 0; j < 4; ++j) {
                float xl, xh; unpack2(acc[i][j], xl, xh);
                sv[i][j] = (xl + xh) * SCALE;
            }

        /* online softmax: reduce over the 16 lanes of a half-warp (same rows) */
        float rs[4];
#pragma unroll
        for (int i = 0; i < 4; ++i) {
            float rmax = fmaxf(fmaxf(sv[i][0], sv[i][1]), fmaxf(sv[i][2], sv[i][3]));
#pragma unroll
            for (int m = 8; m >= 1; m >>= 1)
                rmax = fmaxf(rmax, __shfl_xor_sync(0xffffffffu, rmax, m));
            float mnew = fmaxf(mreg[i], rmax);
            float rsum = 0.f;
#pragma unroll
            for (int j = 0; j < 4; ++j) { sv[i][j] = __expf(sv[i][j] - mnew); rsum += sv[i][j]; }
#pragma unroll
            for (int m = 8; m >= 1; m >>= 1)
                rsum += __shfl_xor_sync(0xffffffffu, rsum, m);
            rs[i] = __expf(mreg[i] - mnew);
            lreg[i] = lreg[i] * rs[i] + rsum;
            mreg[i] = mnew;
#pragma unroll
            for (int j = 0; j < 4; ++j) Ps[(r0 + i) * PSTR + tc + 16 * j] = sv[i][j];
        }
        __syncthreads();

        /* O = O*rs + P V : cols d = 2*tc + 32*m (conflict-free V loads) */
#pragma unroll
        for (int i = 0; i < 4; ++i) {
            ull rs2 = pack2(rs[i], rs[i]);
#pragma unroll
            for (int m = 0; m < 4; ++m) o2[i][m] = fmul2(o2[i][m], rs2);
        }
#pragma unroll 4
        for (int c = 0; c < BC; ++c) {
            ull pd[4], vv[4];
#pragma unroll
            for (int i = 0; i < 4; ++i) {
                float p = Ps[(r0 + i) * PSTR + c];
                pd[i] = pack2(p, p);
            }
#pragma unroll
            for (int m = 0; m < 4; ++m)
                vv[m] = *(const ull*)(Vs + c * KSTR + 2 * tc + 32 * m);
#pragma unroll
            for (int i = 0; i < 4; ++i)
#pragma unroll
                for (int m = 0; m < 4; ++m)
                    o2[i][m] = ffma2(pd[i], vv[m], o2[i][m]);
        }
    }

    /* epilogue: normalize and store */
#pragma unroll
    for (int i = 0; i < 4; ++i) {
        float inv = 1.0f / lreg[i];
        ull inv2 = pack2(inv, inv);
        float* orow = out + (size_t)(qbase + r0 + i) * (NH * HD) + h * HD;
#pragma unroll
        for (int m = 0; m < 4; ++m) {
            ull v = fmul2(o2[i][m], inv2);
            *(ull*)(orow + 2 * tc + 32 * m) = v;
        }
    }
}

/* ------------------------------------------------------------------ */
extern "C" void kernel_launch(void* const* d_in, const int* in_sizes, int n_in,
                              void* d_out, int out_size)
{
    (void)in_sizes; (void)n_in; (void)out_size;
    const float* x  = (const float*)d_in[0];
    const float* qw = (const float*)d_in[1];
    const float* kw = (const float*)d_in[2];
    const float* f1 = (const float*)d_in[3];
    const float* f2 = (const float*)d_in[4];

    dim3 pb(64, NH);
    prep_kernel<<<NTOK, pb>>>(x, qw, kw, f1, f2);

    const int smem = (3 * BR * KSTR + BR * PSTR) * (int)sizeof(float); /* 116736 B */
    cudaFuncSetAttribute(attn_kernel, cudaFuncAttributeMaxDynamicSharedMemorySize, smem);
    dim3 ag(NTOK / BR, NH);
    attn_kernel<<<ag, ATHREADS, smem>>>((float*)d_out);
}

// round 2
// speedup vs baseline: 1.0003x; 1.0003x over previous
#include <cuda_runtime.h>
#include <math.h>

#define NTOK 4096
#define NH   16
#define HD   128
#define TXT  3072
#define SCALE 0.088388347648318447f  /* 128^-0.5 */

#define BR 64
#define BC 64
#define KSTR 130   /* smem row stride (floats) for Q/K/V tiles: pad 2 -> conflict-free, 8B aligned */
#define PSTR 66    /* smem row stride for P tile */
#define ATHREADS 256

typedef unsigned long long ull;

/* scratch: Q,K,V in [head][token][dim] layout (fp32) */
__device__ float Qg[(size_t)NH * NTOK * HD];
__device__ float Kg[(size_t)NH * NTOK * HD];
__device__ float Vg[(size_t)NH * NTOK * HD];

__device__ __forceinline__ ull pack2(float x, float y) {
    ull r; asm("mov.b64 %0, {%1,%2};" : "=l"(r) : "f"(x), "f"(y)); return r;
}
__device__ __forceinline__ void unpack2(ull v, float& x, float& y) {
    asm("mov.b64 {%0,%1}, %2;" : "=f"(x), "=f"(y) : "l"(v));
}
__device__ __forceinline__ ull ffma2(ull a, ull b, ull c) {
    ull d; asm("fma.rn.f32x2 %0, %1, %2, %3;" : "=l"(d) : "l"(a), "l"(b), "l"(c)); return d;
}
__device__ __forceinline__ ull fmul2(ull a, ull b) {
    ull d; asm("mul.rn.f32x2 %0, %1, %2;" : "=l"(d) : "l"(a), "l"(b)); return d;
}

/* ------------------------------------------------------------------ */
/* prep: qkv split + rmsnorm(q,k) + rope(q,k) + copy v                 */
/* grid: NTOK blocks, block (64,16): tx = rope pair, ty = head         */
/* ------------------------------------------------------------------ */
__global__ void prep_kernel(const float* __restrict__ x,
                            const float* __restrict__ qw,
                            const float* __restrict__ kw,
                            const float* __restrict__ f1,
                            const float* __restrict__ f2)
{
    const int n = blockIdx.x;
    const int h = threadIdx.y;
    const int i = threadIdx.x;   /* pair index 0..63 */

    const float* base = x + (size_t)n * (3 * NH * HD) + h * HD + 2 * i;
    float2 q2 = *(const float2*)(base);
    float2 k2 = *(const float2*)(base + NH * HD);
    float2 v2 = *(const float2*)(base + 2 * NH * HD);

    float sq = q2.x * q2.x + q2.y * q2.y;
    float sk = k2.x * k2.x + k2.y * k2.y;
#pragma unroll
    for (int m = 16; m >= 1; m >>= 1) {
        sq += __shfl_xor_sync(0xffffffffu, sq, m);
        sk += __shfl_xor_sync(0xffffffffu, sk, m);
    }
    __shared__ float red[NH][2][2];
    if ((i & 31) == 0) { red[h][i >> 5][0] = sq; red[h][i >> 5][1] = sk; }
    __syncthreads();
    sq = red[h][0][0] + red[h][1][0];
    sk = red[h][0][1] + red[h][1][1];

    const float rq = rsqrtf(sq * (1.0f / 128.0f) + 1e-5f);
    const float rk = rsqrtf(sk * (1.0f / 128.0f) + 1e-5f);
    float2 wq = *(const float2*)(qw + 2 * i);
    float2 wk = *(const float2*)(kw + 2 * i);
    float qx = q2.x * rq * wq.x, qy = q2.y * rq * wq.y;
    float kx = k2.x * rk * wk.x, ky = k2.y * rk * wk.y;

    float th = (n < TXT) ? f1[n * 64 + i] : f2[(n - TXT) * 64 + i];
    float sn, cs;
    sincosf(th, &sn, &cs);

    float2 qo = make_float2(qx * cs - qy * sn, qx * sn + qy * cs);
    float2 ko = make_float2(kx * cs - ky * sn, kx * sn + ky * cs);

    size_t off = ((size_t)h * NTOK + n) * HD + 2 * i;
    *(float2*)(Qg + off) = qo;
    *(float2*)(Kg + off) = ko;
    *(float2*)(Vg + off) = v2;
}

/* ------------------------------------------------------------------ */
/* flash attention, fp32, FFMA2 inner loops                            */
/* grid: (N/BR, NH), 256 threads. Thread t: row-group tr=t>>4 owns     */
/* rows r0..r0+3 in BOTH gemm phases (m/l/rescale in registers).       */
/* ------------------------------------------------------------------ */
__global__ void __launch_bounds__(ATHREADS, 1)
attn_kernel(float* __restrict__ out)
{
    extern __shared__ float sm[];
    float* Qs = sm;                    /* BR * KSTR */
    float* Ks = Qs + BR * KSTR;        /* BC * KSTR */
    float* Vs = Ks + BC * KSTR;        /* BC * KSTR */
    float* Ps = Vs + BC * KSTR;        /* BR * PSTR */

    const int h = blockIdx.y;
    const int qt = blockIdx.x;
    const int t = threadIdx.x;
    const int qbase = qt * BR;

    const float* Qh = Qg + ((size_t)h * NTOK + qbase) * HD;
    const float* Kh = Kg + (size_t)h * NTOK * HD;
    const float* Vh = Vg + (size_t)h * NTOK * HD;

    /* load Q tile (64 x 128) */
#pragma unroll
    for (int u = 0; u < 8; ++u) {
        int idx = t + u * ATHREADS;          /* 0..2047: 64 rows x 32 float4 */
        int r = idx >> 5, c4 = (idx & 31) << 2;
        float4 v = *(const float4*)(Qh + r * HD + c4);
        float* d = Qs + r * KSTR + c4;
        *(float2*)(d)     = make_float2(v.x, v.y);
        *(float2*)(d + 2) = make_float2(v.z, v.w);
    }

    const int tr = t >> 4;     /* 0..15 */
    const int tc = t & 15;     /* 0..15 */
    const int r0 = tr * 4;

    ull o2[4][4];
    float mreg[4], lreg[4];
#pragma unroll
    for (int i = 0; i < 4; ++i) {
        mreg[i] = __int_as_float(0xff800000); /* -inf */
        lreg[i] = 0.f;
#pragma unroll
        for (int m = 0; m < 4; ++m) o2[i][m] = 0ull;
    }

    for (int kt = 0; kt < NTOK / BC; ++kt) {
        __syncthreads();   /* previous iter done with Ks/Vs/Ps */
        const float* Kt = Kh + (size_t)kt * BC * HD;
        const float* Vt = Vh + (size_t)kt * BC * HD;
#pragma unroll
        for (int u = 0; u < 8; ++u) {
            int idx = t + u * ATHREADS;
            int r = idx >> 5, c4 = (idx & 31) << 2;
            float4 kv = *(const float4*)(Kt + r * HD + c4);
            float4 vv = *(const float4*)(Vt + r * HD + c4);
            float* dk = Ks + r * KSTR + c4;
            float* dv = Vs + r * KSTR + c4;
            *(float2*)(dk)     = make_float2(kv.x, kv.y);
            *(float2*)(dk + 2) = make_float2(kv.z, kv.w);
            *(float2*)(dv)     = make_float2(vv.x, vv.y);
            *(float2*)(dv + 2) = make_float2(vv.z, vv.w);
        }
        __syncthreads();

        /* S = Q K^T : rows r0+i, cols tc+16j (conflict-free K loads) */
        ull acc[4][4];
#pragma unroll
        for (int i = 0; i < 4; ++i)
#pragma unroll
            for (int j = 0; j < 4; ++j) acc[i][j] = 0ull;

#pragma unroll 4
        for (int d = 0; d < HD; d += 2) {
            ull qa[4], kb[4];
#pragma unroll
            for (int i = 0; i < 4; ++i) qa[i] = *(const ull*)(Qs + (r0 + i) * KSTR + d);
#pragma unroll
            for (int j = 0; j < 4; ++j) kb[j] = *(const ull*)(Ks + (tc + 16 * j) * KSTR + d);
#pragma unroll
            for (int i = 0; i < 4; ++i)
#pragma unroll
                for (int j = 0; j < 4; ++j)
                    acc[i][j] = ffma2(qa[i], kb[j], acc[i][j]);
        }

        float sv[4][4];
#pragma unroll
        for (int i = 0; i < 4; ++i)
#pragma unroll
            for (int j = 0; j < 4; ++j) {
                float xl, xh; unpack2(acc[i][j], xl, xh);
                sv[i][j] = (xl + xh) * SCALE;
            }

        /* online softmax: reduce over the 16 lanes of a half-warp (same rows) */
        float rs[4];
#pragma unroll
        for (int i = 0; i < 4; ++i) {
            float rmax = fmaxf(fmaxf(sv[i][0], sv[i][1]), fmaxf(sv[i][2], sv[i][3]));
#pragma unroll
            for (int m = 8; m >= 1; m >>= 1)
                rmax = fmaxf(rmax, __shfl_xor_sync(0xffffffffu, rmax, m));
            float mnew = fmaxf(mreg[i], rmax);
            float rsum = 0.f;
#pragma unroll
            for (int j = 0; j < 4; ++j) { sv[i][j] = __expf(sv[i][j] - mnew); rsum += sv[i][j]; }
#pragma unroll
            for (int m = 8; m >= 1; m >>= 1)
                rsum += __shfl_xor_sync(0xffffffffu, rsum, m);
            rs[i] = __expf(mreg[i] - mnew);
            lreg[i] = lreg[i] * rs[i] + rsum;
            mreg[i] = mnew;
#pragma unroll
            for (int j = 0; j < 4; ++j) Ps[(r0 + i) * PSTR + tc + 16 * j] = sv[i][j];
        }
        __syncthreads();

        /* O = O*rs + P V : cols d = 2*tc + 32*m (conflict-free V loads) */
#pragma unroll
        for (int i = 0; i < 4; ++i) {
            ull rs2 = pack2(rs[i], rs[i]);
#pragma unroll
            for (int m = 0; m < 4; ++m) o2[i][m] = fmul2(o2[i][m], rs2);
        }
#pragma unroll 4
        for (int c = 0; c < BC; ++c) {
            ull pd[4], vv[4];
#pragma unroll
            for (int i = 0; i < 4; ++i) {
                float p = Ps[(r0 + i) * PSTR + c];
                pd[i] = pack2(p, p);
            }
#pragma unroll
            for (int m = 0; m < 4; ++m)
                vv[m] = *(const ull*)(Vs + c * KSTR + 2 * tc + 32 * m);
#pragma unroll
            for (int i = 0; i < 4; ++i)
#pragma unroll
                for (int m = 0; m < 4; ++m)
                    o2[i][m] = ffma2(pd[i], vv[m], o2[i][m]);
        }
    }

    /* epilogue: normalize and store */
#pragma unroll
    for (int i = 0; i < 4; ++i) {
        float inv = 1.0f / lreg[i];
        ull inv2 = pack2(inv, inv);
        float* orow = out + (size_t)(qbase + r0 + i) * (NH * HD) + h * HD;
#pragma unroll
        for (int m = 0; m < 4; ++m) {
            ull v = fmul2(o2[i][m], inv2);
            *(ull*)(orow + 2 * tc + 32 * m) = v;
        }
    }
}

/* ------------------------------------------------------------------ */
extern "C" void kernel_launch(void* const* d_in, const int* in_sizes, int n_in,
                              void* d_out, int out_size)
{
    (void)in_sizes; (void)n_in; (void)out_size;
    const float* x  = (const float*)d_in[0];
    const float* qw = (const float*)d_in[1];
    const float* kw = (const float*)d_in[2];
    const float* f1 = (const float*)d_in[3];
    const float* f2 = (const float*)d_in[4];

    dim3 pb(64, NH);
    prep_kernel<<<NTOK, pb>>>(x, qw, kw, f1, f2);

    const int smem = (3 * BR * KSTR + BR * PSTR) * (int)sizeof(float); /* 116736 B */
    cudaFuncSetAttribute(attn_kernel, cudaFuncAttributeMaxDynamicSharedMemorySize, smem);
    dim3 ag(NTOK / BR, NH);
    attn_kernel<<<ag, ATHREADS, smem>>>((float*)d_out);
}

// round 3
// speedup vs baseline: 2.6358x; 2.6349x over previous
#include <cuda_runtime.h>
#include <cuda_bf16.h>
#include <math.h>

#define NTOK 4096
#define NH   16
#define HD   128
#define TXT  3072
#define SCALE 0.088388347648318447f  /* 128^-0.5 */

#define BR 128
#define BC 64
#define KST 136                 /* smem row stride (bf16 elems): conflict-free */
#define TILE (BC * KST)         /* 8704 bf16 elems per tile */
#define THREADS 256
#define NKT (NTOK / BC)         /* 64 */

typedef unsigned int u32;
typedef unsigned short u16;

/* split-bf16 scratch: Q/K layout [h][n][d], V layout [h][n][d] */
__device__ __nv_bfloat16 Qhi_g[NH * NTOK * HD];
__device__ __nv_bfloat16 Qlo_g[NH * NTOK * HD];
__device__ __nv_bfloat16 Khi_g[NH * NTOK * HD];
__device__ __nv_bfloat16 Klo_g[NH * NTOK * HD];
__device__ __nv_bfloat16 Vhi_g[NH * NTOK * HD];
__device__ __nv_bfloat16 Vlo_g[NH * NTOK * HD];

/* pack two f32 -> bf16x2 reg, low 16 bits = 'lo' argument */
__device__ __forceinline__ u32 packbf(float lo, float hi) {
    u32 r; asm("cvt.rn.bf16x2.f32 %0, %1, %2;" : "=r"(r) : "f"(hi), "f"(lo));
    return r;
}
/* residual (x - bf16(x)) pair, packed */
__device__ __forceinline__ u32 residbf(float lo, float hi, u32 hipack) {
    float h0 = __uint_as_float(hipack << 16);
    float h1 = __uint_as_float(hipack & 0xffff0000u);
    return packbf(lo - h0, hi - h1);
}

__device__ __forceinline__ void mma_bf16(float* c, const u32* a, u32 b0, u32 b1) {
    asm("mma.sync.aligned.m16n8k16.row.col.f32.bf16.bf16.f32 "
        "{%0,%1,%2,%3}, {%4,%5,%6,%7}, {%8,%9}, {%0,%1,%2,%3};"
        : "+f"(c[0]), "+f"(c[1]), "+f"(c[2]), "+f"(c[3])
        : "r"(a[0]), "r"(a[1]), "r"(a[2]), "r"(a[3]), "r"(b0), "r"(b1));
}

__device__ __forceinline__ void cpa16(u32 saddr, const void* g) {
    asm volatile("cp.async.cg.shared.global [%0], [%1], 16;" :: "r"(saddr), "l"(g) : "memory");
}

/* ------------------------------------------------------------------ */
/* prep: split + rmsnorm(q,k) + rope(q,k) -> split-bf16 hi/lo arrays   */
/* grid: NTOK blocks, block (64,16): tx = rope pair, ty = head         */
/* ------------------------------------------------------------------ */
__global__ void prep_kernel(const float* __restrict__ x,
                            const float* __restrict__ qw,
                            const float* __restrict__ kw,
                            const float* __restrict__ f1,
                            const float* __restrict__ f2)
{
    const int n = blockIdx.x;
    const int h = threadIdx.y;
    const int i = threadIdx.x;   /* pair index 0..63 */

    const float* base = x + (size_t)n * (3 * NH * HD) + h * HD + 2 * i;
    float2 q2 = *(const float2*)(base);
    float2 k2 = *(const float2*)(base + NH * HD);
    float2 v2 = *(const float2*)(base + 2 * NH * HD);

    float sq = q2.x * q2.x + q2.y * q2.y;
    float sk = k2.x * k2.x + k2.y * k2.y;
#pragma unroll
    for (int m = 16; m >= 1; m >>= 1) {
        sq += __shfl_xor_sync(0xffffffffu, sq, m);
        sk += __shfl_xor_sync(0xffffffffu, sk, m);
    }
    __shared__ float red[NH][2][2];
    if ((i & 31) == 0) { red[h][i >> 5][0] = sq; red[h][i >> 5][1] = sk; }
    __syncthreads();
    sq = red[h][0][0] + red[h][1][0];
    sk = red[h][0][1] + red[h][1][1];

    const float rq = rsqrtf(sq * (1.0f / 128.0f) + 1e-5f);
    const float rk = rsqrtf(sk * (1.0f / 128.0f) + 1e-5f);
    float2 wq = *(const float2*)(qw + 2 * i);
    float2 wk = *(const float2*)(kw + 2 * i);
    float qx = q2.x * rq * wq.x, qy = q2.y * rq * wq.y;
    float kx = k2.x * rk * wk.x, ky = k2.y * rk * wk.y;

    float th = (n < TXT) ? f1[n * 64 + i] : f2[(n - TXT) * 64 + i];
    float sn, cs;
    sincosf(th, &sn, &cs);

    float qox = qx * cs - qy * sn, qoy = qx * sn + qy * cs;
    float kox = kx * cs - ky * sn, koy = kx * sn + ky * cs;

    int w = ((h * NTOK + n) * HD + 2 * i) >> 1;   /* u32 word index */
    u32 qh = packbf(qox, qoy);
    ((u32*)Qhi_g)[w] = qh;
    ((u32*)Qlo_g)[w] = residbf(qox, qoy, qh);
    u32 kh = packbf(kox, koy);
    ((u32*)Khi_g)[w] = kh;
    ((u32*)Klo_g)[w] = residbf(kox, koy, kh);
    u32 vh = packbf(v2.x, v2.y);
    ((u32*)Vhi_g)[w] = vh;
    ((u32*)Vlo_g)[w] = residbf(v2.x, v2.y, vh);
}

/* ------------------------------------------------------------------ */
__device__ __forceinline__ void issue_tile(int h, int kt, int buf, int t, u32 smbase)
{
    int kb = (h * NTOK + kt * BC) * HD;
    u32 sb = smbase + (u32)buf * (4u * TILE * 2u);
#pragma unroll
    for (int u = 0; u < 4; ++u) {
        int c = t + u * THREADS;          /* 0..1023 chunks of 16B */
        int r = c >> 4, col = c & 15;
        int go = kb + r * HD + col * 8;
        u32 so = sb + (u32)(r * KST + col * 8) * 2u;
        cpa16(so,                Khi_g + go);
        cpa16(so + TILE * 2,     Klo_g + go);
        cpa16(so + 2 * TILE * 2, Vhi_g + go);
        cpa16(so + 3 * TILE * 2, Vlo_g + go);
    }
    asm volatile("cp.async.commit_group;" ::: "memory");
}

extern __shared__ __nv_bfloat16 smbuf[];

__global__ void __launch_bounds__(THREADS, 1)
attn_kernel(float* __restrict__ out)
{
    const int h = blockIdx.y;
    const int qt = blockIdx.x;
    const int t = threadIdx.x;
    const int warp = t >> 5, lane = t & 31;
    const int gid = lane >> 2, ctid = lane & 3;
    const int qbase = qt * BR;
    const int ra = qbase + warp * 16 + gid;   /* row a; row b = ra + 8 */

    u32 smbase = (u32)__cvta_generic_to_shared(smbuf);

    /* preload Q fragments (hi/lo) into registers */
    u32 qh[8][4], ql[8][4];
    {
        const u32* Qh32 = (const u32*)Qhi_g;
        const u32* Ql32 = (const u32*)Qlo_g;
        int base = (h * NTOK + ra) * HD;
#pragma unroll
        for (int ks = 0; ks < 8; ++ks) {
            int c0 = ks * 16 + ctid * 2;
            qh[ks][0] = Qh32[(base + c0) >> 1];
            qh[ks][1] = Qh32[(base + 8 * HD + c0) >> 1];
            qh[ks][2] = Qh32[(base + c0 + 8) >> 1];
            qh[ks][3] = Qh32[(base + 8 * HD + c0 + 8) >> 1];
            ql[ks][0] = Ql32[(base + c0) >> 1];
            ql[ks][1] = Ql32[(base + 8 * HD + c0) >> 1];
            ql[ks][2] = Ql32[(base + c0 + 8) >> 1];
            ql[ks][3] = Ql32[(base + 8 * HD + c0 + 8) >> 1];
        }
    }

    float o[16][4];
#pragma unroll
    for (int i = 0; i < 16; ++i)
#pragma unroll
        for (int j = 0; j < 4; ++j) o[i][j] = 0.f;
    float m_a = -INFINITY, m_b = -INFINITY, l_a = 0.f, l_b = 0.f;

    issue_tile(h, 0, 0, t, smbase);

#pragma unroll 1
    for (int kt = 0; kt < NKT; ++kt) {
        if (kt + 1 < NKT) issue_tile(h, kt + 1, (kt + 1) & 1, t, smbase);
        if (kt + 1 < NKT) asm volatile("cp.async.wait_group 1;" ::: "memory");
        else              asm volatile("cp.async.wait_group 0;" ::: "memory");
        __syncthreads();

        const __nv_bfloat16* base_s = smbuf + (kt & 1) * 4 * TILE;
        const u32* Kh32 = (const u32*)(base_s);
        const u32* Kl32 = (const u32*)(base_s + TILE);
        const u16* Vh16 = (const u16*)(base_s + 2 * TILE);
        const u16* Vl16 = (const u16*)(base_s + 3 * TILE);

        /* ---- S = Q K^T (3x split-bf16 MMAs) ---- */
        float s[8][4];
#pragma unroll
        for (int nt = 0; nt < 8; ++nt)
#pragma unroll
            for (int j = 0; j < 4; ++j) s[nt][j] = 0.f;

#pragma unroll
        for (int ks = 0; ks < 8; ++ks) {
#pragma unroll
            for (int nt = 0; nt < 8; ++nt) {
                int wi = (nt * 8 + gid) * (KST / 2) + ks * 8 + ctid;
                u32 bh0 = Kh32[wi], bh1 = Kh32[wi + 4];
                u32 bl0 = Kl32[wi], bl1 = Kl32[wi + 4];
                mma_bf16(s[nt], qh[ks], bh0, bh1);
                mma_bf16(s[nt], qh[ks], bl0, bl1);
                mma_bf16(s[nt], ql[ks], bh0, bh1);
            }
        }

        /* ---- online softmax (rows ra, ra+8 live in lanes sharing gid) ---- */
        float rmax_a = -INFINITY, rmax_b = -INFINITY;
#pragma unroll
        for (int nt = 0; nt < 8; ++nt) {
#pragma unroll
            for (int j = 0; j < 4; ++j) s[nt][j] *= SCALE;
            rmax_a = fmaxf(rmax_a, fmaxf(s[nt][0], s[nt][1]));
            rmax_b = fmaxf(rmax_b, fmaxf(s[nt][2], s[nt][3]));
        }
#pragma unroll
        for (int mk = 1; mk <= 2; mk <<= 1) {
            rmax_a = fmaxf(rmax_a, __shfl_xor_sync(0xffffffffu, rmax_a, mk));
            rmax_b = fmaxf(rmax_b, __shfl_xor_sync(0xffffffffu, rmax_b, mk));
        }
        float na = fmaxf(m_a, rmax_a), nb = fmaxf(m_b, rmax_b);
        float rs_a = __expf(m_a - na), rs_b = __expf(m_b - nb);
        float sum_a = 0.f, sum_b = 0.f;
#pragma unroll
        for (int nt = 0; nt < 8; ++nt) {
            s[nt][0] = __expf(s[nt][0] - na);
            s[nt][1] = __expf(s[nt][1] - na);
            s[nt][2] = __expf(s[nt][2] - nb);
            s[nt][3] = __expf(s[nt][3] - nb);
            sum_a += s[nt][0] + s[nt][1];
            sum_b += s[nt][2] + s[nt][3];
        }
#pragma unroll
        for (int mk = 1; mk <= 2; mk <<= 1) {
            sum_a += __shfl_xor_sync(0xffffffffu, sum_a, mk);
            sum_b += __shfl_xor_sync(0xffffffffu, sum_b, mk);
        }
        l_a = l_a * rs_a + sum_a; m_a = na;
        l_b = l_b * rs_b + sum_b; m_b = nb;
#pragma unroll
        for (int i = 0; i < 16; ++i) {
            o[i][0] *= rs_a; o[i][1] *= rs_a;
            o[i][2] *= rs_b; o[i][3] *= rs_b;
        }

        /* ---- O += P V (3x split-bf16 MMAs, P register-resident) ---- */
#pragma unroll
        for (int kk = 0; kk < 4; ++kk) {
            u32 pah[4], pal[4];
            pah[0] = packbf(s[2 * kk][0], s[2 * kk][1]);
            pal[0] = residbf(s[2 * kk][0], s[2 * kk][1], pah[0]);
            pah[1] = packbf(s[2 * kk][2], s[2 * kk][3]);
            pal[1] = residbf(s[2 * kk][2], s[2 * kk][3], pah[1]);
            pah[2] = packbf(s[2 * kk + 1][0], s[2 * kk + 1][1]);
            pal[2] = residbf(s[2 * kk + 1][0], s[2 * kk + 1][1], pah[2]);
            pah[3] = packbf(s[2 * kk + 1][2], s[2 * kk + 1][3]);
            pal[3] = residbf(s[2 * kk + 1][2], s[2 * kk + 1][3], pah[3]);
#pragma unroll
            for (int nt2 = 0; nt2 < 16; ++nt2) {
                int e0 = (kk * 16 + ctid * 2) * KST + nt2 * 8 + gid;
                u32 bh0 = (u32)Vh16[e0] | ((u32)Vh16[e0 + KST] << 16);
                u32 bh1 = (u32)Vh16[e0 + 8 * KST] | ((u32)Vh16[e0 + 9 * KST] << 16);
                u32 bl0 = (u32)Vl16[e0] | ((u32)Vl16[e0 + KST] << 16);
                u32 bl1 = (u32)Vl16[e0 + 8 * KST] | ((u32)Vl16[e0 + 9 * KST] << 16);
                mma_bf16(o[nt2], pah, bh0, bh1);
                mma_bf16(o[nt2], pah, bl0, bl1);
                mma_bf16(o[nt2], pal, bh0, bh1);
            }
        }
        __syncthreads();   /* protect buffer before next issue overwrites it */
    }

    /* ---- epilogue ---- */
    float ia = 1.f / l_a, ib = 1.f / l_b;
    float* orow_a = out + (size_t)ra * (NH * HD) + h * HD;
    float* orow_b = orow_a + (size_t)8 * (NH * HD);
#pragma unroll
    for (int nt2 = 0; nt2 < 16; ++nt2) {
        int col = nt2 * 8 + 2 * ctid;
        *(float2*)(orow_a + col) = make_float2(o[nt2][0] * ia, o[nt2][1] * ia);
        *(float2*)(orow_b + col) = make_float2(o[nt2][2] * ib, o[nt2][3] * ib);
    }
}

/* ------------------------------------------------------------------ */
extern "C" void kernel_launch(void* const* d_in, const int* in_sizes, int n_in,
                              void* d_out, int out_size)
{
    (void)in_sizes; (void)n_in; (void)out_size;
    const float* x  = (const float*)d_in[0];
    const float* qw = (const float*)d_in[1];
    const float* kw = (const float*)d_in[2];
    const float* f1 = (const float*)d_in[3];
    const float* f2 = (const float*)d_in[4];

    dim3 pb(64, NH);
    prep_kernel<<<NTOK, pb>>>(x, qw, kw, f1, f2);

    const int smem = 2 * 4 * TILE * (int)sizeof(__nv_bfloat16);  /* 139264 B */
    cudaFuncSetAttribute(attn_kernel, cudaFuncAttributeMaxDynamicSharedMemorySize, smem);
    dim3 ag(NTOK / BR, NH);
    attn_kernel<<<ag, THREADS, smem>>>((float*)d_out);
}

// round 4
// speedup vs baseline: 3.0031x; 1.1394x over previous
#include <cuda_runtime.h>
#include <cuda_bf16.h>
#include <math.h>

#define NTOK 4096
#define NH   16
#define HD   128
#define TXT  3072
/* SCALE * log2(e): logits computed directly in log2 domain */
#define QSCALE 0.12752792696929322f

#define BR 128
#define BC 64
#define KST 136                 /* K smem row stride (bf16): 68 words == 4 mod 32 */
#define VST 72                  /* V^T smem row stride (bf16): 36 words == 4 mod 32 */
#define TILE_K (BC * KST)       /* 8704 elems */
#define TILE_V (HD * VST)       /* 9216 elems */
#define BUFSZ  (2 * TILE_K + 2 * TILE_V)   /* 35840 elems per buffer */
#define THREADS 256
#define NKT (NTOK / BC)         /* 64 */

typedef unsigned int u32;

/* split-bf16 scratch. Q/K: [h][n][d].  V: transposed [h][d][n]. */
__device__ __nv_bfloat16 Qhi_g[NH * NTOK * HD];
__device__ __nv_bfloat16 Qlo_g[NH * NTOK * HD];
__device__ __nv_bfloat16 Khi_g[NH * NTOK * HD];
__device__ __nv_bfloat16 Klo_g[NH * NTOK * HD];
__device__ __nv_bfloat16 VhiT_g[NH * HD * NTOK];
__device__ __nv_bfloat16 VloT_g[NH * HD * NTOK];

/* pack two f32 -> bf16x2 reg, low 16 bits = 'lo' argument */
__device__ __forceinline__ u32 packbf(float lo, float hi) {
    u32 r; asm("cvt.rn.bf16x2.f32 %0, %1, %2;" : "=r"(r) : "f"(hi), "f"(lo));
    return r;
}
/* residual (x - bf16(x)) pair, packed */
__device__ __forceinline__ u32 residbf(float lo, float hi, u32 hipack) {
    float h0 = __uint_as_float(hipack << 16);
    float h1 = __uint_as_float(hipack & 0xffff0000u);
    return packbf(lo - h0, hi - h1);
}

__device__ __forceinline__ void mma_bf16(float* c, const u32* a, u32 b0, u32 b1) {
    asm("mma.sync.aligned.m16n8k16.row.col.f32.bf16.bf16.f32 "
        "{%0,%1,%2,%3}, {%4,%5,%6,%7}, {%8,%9}, {%0,%1,%2,%3};"
        : "+f"(c[0]), "+f"(c[1]), "+f"(c[2]), "+f"(c[3])
        : "r"(a[0]), "r"(a[1]), "r"(a[2]), "r"(a[3]), "r"(b0), "r"(b1));
}

__device__ __forceinline__ void cpa16(u32 saddr, const void* g) {
    asm volatile("cp.async.cg.shared.global [%0], [%1], 16;" :: "r"(saddr), "l"(g) : "memory");
}

/* ------------------------------------------------------------------ */
/* prep: split + rmsnorm(q,k) + rope(q,k) -> split-bf16. Q pre-scaled. */
/* ------------------------------------------------------------------ */
__global__ void prep_kernel(const float* __restrict__ x,
                            const float* __restrict__ qw,
                            const float* __restrict__ kw,
                            const float* __restrict__ f1,
                            const float* __restrict__ f2)
{
    const int n = blockIdx.x;
    const int h = threadIdx.y;
    const int i = threadIdx.x;   /* pair index 0..63 */

    const float* base = x + (size_t)n * (3 * NH * HD) + h * HD + 2 * i;
    float2 q2 = *(const float2*)(base);
    float2 k2 = *(const float2*)(base + NH * HD);

    float sq = q2.x * q2.x + q2.y * q2.y;
    float sk = k2.x * k2.x + k2.y * k2.y;
#pragma unroll
    for (int m = 16; m >= 1; m >>= 1) {
        sq += __shfl_xor_sync(0xffffffffu, sq, m);
        sk += __shfl_xor_sync(0xffffffffu, sk, m);
    }
    __shared__ float red[NH][2][2];
    if ((i & 31) == 0) { red[h][i >> 5][0] = sq; red[h][i >> 5][1] = sk; }
    __syncthreads();
    sq = red[h][0][0] + red[h][1][0];
    sk = red[h][0][1] + red[h][1][1];

    const float rq = rsqrtf(sq * (1.0f / 128.0f) + 1e-5f);
    const float rk = rsqrtf(sk * (1.0f / 128.0f) + 1e-5f);
    float2 wq = *(const float2*)(qw + 2 * i);
    float2 wk = *(const float2*)(kw + 2 * i);
    float qx = q2.x * rq * wq.x, qy = q2.y * rq * wq.y;
    float kx = k2.x * rk * wk.x, ky = k2.y * rk * wk.y;

    float th = (n < TXT) ? f1[n * 64 + i] : f2[(n - TXT) * 64 + i];
    float sn, cs;
    sincosf(th, &sn, &cs);

    float qox = (qx * cs - qy * sn) * QSCALE;
    float qoy = (qx * sn + qy * cs) * QSCALE;
    float kox = kx * cs - ky * sn, koy = kx * sn + ky * cs;

    int w = ((h * NTOK + n) * HD + 2 * i) >> 1;   /* u32 word index */
    u32 qh = packbf(qox, qoy);
    ((u32*)Qhi_g)[w] = qh;
    ((u32*)Qlo_g)[w] = residbf(qox, qoy, qh);
    u32 kh = packbf(kox, koy);
    ((u32*)Khi_g)[w] = kh;
    ((u32*)Klo_g)[w] = residbf(kox, koy, kh);
}

/* ------------------------------------------------------------------ */
/* vtrans: read V slice of x [n][d], split to bf16 hi/lo, write [h][d][n] */
/* grid (NTOK/64, HD/64, NH), 256 threads, 64x64 fp32 tile in smem      */
/* ------------------------------------------------------------------ */
__global__ void vtrans_kernel(const float* __restrict__ x)
{
    __shared__ float tl[64][65];
    const int nt = blockIdx.x, dt = blockIdx.y, h = blockIdx.z;
    const int t = threadIdx.x;

    const float* src = x + (size_t)(nt * 64) * (3 * NH * HD)
                         + 2 * NH * HD + h * HD + dt * 64;
#pragma unroll
    for (int u = 0; u < 4; ++u) {
        int idx = t + u * THREADS;        /* 0..1023: 64 rows x 16 float4 */
        int r = idx >> 4, c4 = (idx & 15) << 2;
        float4 v = *(const float4*)(src + (size_t)r * (3 * NH * HD) + c4);
        tl[r][c4] = v.x; tl[r][c4 + 1] = v.y; tl[r][c4 + 2] = v.z; tl[r][c4 + 3] = v.w;
    }
    __syncthreads();

    u32* dhi = (u32*)VhiT_g;
    u32* dlo = (u32*)VloT_g;
#pragma unroll
    for (int u = 0; u < 8; ++u) {
        int widx = t + u * THREADS;       /* 0..2047: 64 d-rows x 32 words */
        int dr = widx >> 5, nw = widx & 31;
        float v0 = tl[2 * nw][dr], v1 = tl[2 * nw + 1][dr];
        u32 hp = packbf(v0, v1);
        int w = (((h * HD + dt * 64 + dr) * NTOK) >> 1) + nt * 32 + nw;
        dhi[w] = hp;
        dlo[w] = residbf(v0, v1, hp);
    }
}

/* ------------------------------------------------------------------ */
__device__ __forceinline__ void issue_tile(int h, int kt, int buf, int t, u32 smbase)
{
    int kb = (h * NTOK + kt * BC) * HD;            /* K elem base */
    int vb = h * HD * NTOK + kt * BC;              /* V^T elem base (col offset) */
    u32 sb = smbase + (u32)buf * (BUFSZ * 2u);
#pragma unroll
    for (int u = 0; u < 4; ++u) {
        int c = t + u * THREADS;                   /* 0..1023 */
        int rk = c >> 4, ck = c & 15;              /* K: 64 rows x 16 chunks */
        int rv = c >> 3, cv = c & 7;               /* V: 128 rows x 8 chunks */
        int gk = kb + rk * HD + ck * 8;
        int gv = vb + rv * NTOK + cv * 8;
        u32 sk = sb + (u32)(rk * KST + ck * 8) * 2u;
        u32 sv = sb + (u32)(rv * VST + cv * 8) * 2u;
        cpa16(sk,                          Khi_g + gk);
        cpa16(sk + TILE_K * 2,             Klo_g + gk);
        cpa16(sv + 2 * TILE_K * 2,         VhiT_g + gv);
        cpa16(sv + (2 * TILE_K + TILE_V) * 2, VloT_g + gv);
    }
    asm volatile("cp.async.commit_group;" ::: "memory");
}

extern __shared__ __nv_bfloat16 smbuf[];

__global__ void __launch_bounds__(THREADS, 1)
attn_kernel(float* __restrict__ out)
{
    const int h = blockIdx.y;
    const int qt = blockIdx.x;
    const int t = threadIdx.x;
    const int warp = t >> 5, lane = t & 31;
    const int gid = lane >> 2, ctid = lane & 3;
    const int qbase = qt * BR;
    const int ra = qbase + warp * 16 + gid;   /* row a; row b = ra + 8 */

    u32 smbase = (u32)__cvta_generic_to_shared(smbuf);

    /* preload Q fragments (hi/lo, pre-scaled) */
    u32 qh[8][4], ql[8][4];
    {
        const u32* Qh32 = (const u32*)Qhi_g;
        const u32* Ql32 = (const u32*)Qlo_g;
        int base = (h * NTOK + ra) * HD;
#pragma unroll
        for (int ks = 0; ks < 8; ++ks) {
            int c0 = ks * 16 + ctid * 2;
            qh[ks][0] = Qh32[(base + c0) >> 1];
            qh[ks][1] = Qh32[(base + 8 * HD + c0) >> 1];
            qh[ks][2] = Qh32[(base + c0 + 8) >> 1];
            qh[ks][3] = Qh32[(base + 8 * HD + c0 + 8) >> 1];
            ql[ks][0] = Ql32[(base + c0) >> 1];
            ql[ks][1] = Ql32[(base + 8 * HD + c0) >> 1];
            ql[ks][2] = Ql32[(base + c0 + 8) >> 1];
            ql[ks][3] = Ql32[(base + 8 * HD + c0 + 8) >> 1];
        }
    }

    float o[16][4];
#pragma unroll
    for (int i = 0; i < 16; ++i)
#pragma unroll
        for (int j = 0; j < 4; ++j) o[i][j] = 0.f;
    float m_a = -INFINITY, m_b = -INFINITY, l_a = 0.f, l_b = 0.f;

    issue_tile(h, 0, 0, t, smbase);

#pragma unroll 1
    for (int kt = 0; kt < NKT; ++kt) {
        if (kt + 1 < NKT) {
            issue_tile(h, kt + 1, (kt + 1) & 1, t, smbase);
            asm volatile("cp.async.wait_group 1;" ::: "memory");
        } else {
            asm volatile("cp.async.wait_group 0;" ::: "memory");
        }
        __syncthreads();

        const __nv_bfloat16* base_s = smbuf + (kt & 1) * BUFSZ;
        const u32* Kh32 = (const u32*)(base_s);
        const u32* Kl32 = (const u32*)(base_s + TILE_K);
        const u32* Vh32 = (const u32*)(base_s + 2 * TILE_K);
        const u32* Vl32 = (const u32*)(base_s + 2 * TILE_K + TILE_V);

        /* ---- S = Q K^T (3x split-bf16 MMAs), logits in log2 domain ---- */
        float s[8][4];
#pragma unroll
        for (int nt = 0; nt < 8; ++nt)
#pragma unroll
            for (int j = 0; j < 4; ++j) s[nt][j] = 0.f;

#pragma unroll
        for (int ks = 0; ks < 8; ++ks) {
#pragma unroll
            for (int nt = 0; nt < 8; ++nt) {
                int wi = (nt * 8 + gid) * (KST / 2) + ks * 8 + ctid;
                u32 bh0 = Kh32[wi], bh1 = Kh32[wi + 4];
                u32 bl0 = Kl32[wi], bl1 = Kl32[wi + 4];
                mma_bf16(s[nt], qh[ks], bh0, bh1);
                mma_bf16(s[nt], qh[ks], bl0, bl1);
                mma_bf16(s[nt], ql[ks], bh0, bh1);
            }
        }

        /* ---- online softmax (exp2 domain) ---- */
        float rmax_a = -INFINITY, rmax_b = -INFINITY;
#pragma unroll
        for (int nt = 0; nt < 8; ++nt) {
            rmax_a = fmaxf(rmax_a, fmaxf(s[nt][0], s[nt][1]));
            rmax_b = fmaxf(rmax_b, fmaxf(s[nt][2], s[nt][3]));
        }
#pragma unroll
        for (int mk = 1; mk <= 2; mk <<= 1) {
            rmax_a = fmaxf(rmax_a, __shfl_xor_sync(0xffffffffu, rmax_a, mk));
            rmax_b = fmaxf(rmax_b, __shfl_xor_sync(0xffffffffu, rmax_b, mk));
        }
        float na = fmaxf(m_a, rmax_a), nb = fmaxf(m_b, rmax_b);
        float rs_a = exp2f(m_a - na), rs_b = exp2f(m_b - nb);
        float sum_a = 0.f, sum_b = 0.f;
#pragma unroll
        for (int nt = 0; nt < 8; ++nt) {
            s[nt][0] = exp2f(s[nt][0] - na);
            s[nt][1] = exp2f(s[nt][1] - na);
            s[nt][2] = exp2f(s[nt][2] - nb);
            s[nt][3] = exp2f(s[nt][3] - nb);
            sum_a += s[nt][0] + s[nt][1];
            sum_b += s[nt][2] + s[nt][3];
        }
#pragma unroll
        for (int mk = 1; mk <= 2; mk <<= 1) {
            sum_a += __shfl_xor_sync(0xffffffffu, sum_a, mk);
            sum_b += __shfl_xor_sync(0xffffffffu, sum_b, mk);
        }
        l_a = l_a * rs_a + sum_a; m_a = na;
        l_b = l_b * rs_b + sum_b; m_b = nb;
#pragma unroll
        for (int i = 0; i < 16; ++i) {
            o[i][0] *= rs_a; o[i][1] *= rs_a;
            o[i][2] *= rs_b; o[i][3] *= rs_b;
        }

        /* ---- O += P V (3x split-bf16 MMAs, V^T smem: word loads) ---- */
#pragma unroll
        for (int kk = 0; kk < 4; ++kk) {
            u32 pah[4], pal[4];
            pah[0] = packbf(s[2 * kk][0], s[2 * kk][1]);
            pal[0] = residbf(s[2 * kk][0], s[2 * kk][1], pah[0]);
            pah[1] = packbf(s[2 * kk][2], s[2 * kk][3]);
            pal[1] = residbf(s[2 * kk][2], s[2 * kk][3], pah[1]);
            pah[2] = packbf(s[2 * kk + 1][0], s[2 * kk + 1][1]);
            pal[2] = residbf(s[2 * kk + 1][0], s[2 * kk + 1][1], pah[2]);
            pah[3] = packbf(s[2 * kk + 1][2], s[2 * kk + 1][3]);
            pal[3] = residbf(s[2 * kk + 1][2], s[2 * kk + 1][3], pah[3]);
#pragma unroll
            for (int nt2 = 0; nt2 < 16; ++nt2) {
                int wi = (nt2 * 8 + gid) * (VST / 2) + kk * 8 + ctid;
                u32 bh0 = Vh32[wi], bh1 = Vh32[wi + 4];
                u32 bl0 = Vl32[wi], bl1 = Vl32[wi + 4];
                mma_bf16(o[nt2], pah, bh0, bh1);
                mma_bf16(o[nt2], pah, bl0, bl1);
                mma_bf16(o[nt2], pal, bh0, bh1);
            }
        }
        __syncthreads();   /* all reads of this buffer done before reuse */
    }

    /* ---- epilogue ---- */
    float ia = 1.f / l_a, ib = 1.f / l_b;
    float* orow_a = out + (size_t)ra * (NH * HD) + h * HD;
    float* orow_b = orow_a + (size_t)8 * (NH * HD);
#pragma unroll
    for (int nt2 = 0; nt2 < 16; ++nt2) {
        int col = nt2 * 8 + 2 * ctid;
        *(float2*)(orow_a + col) = make_float2(o[nt2][0] * ia, o[nt2][1] * ia);
        *(float2*)(orow_b + col) = make_float2(o[nt2][2] * ib, o[nt2][3] * ib);
    }
}

/* ------------------------------------------------------------------ */
extern "C" void kernel_launch(void* const* d_in, const int* in_sizes, int n_in,
                              void* d_out, int out_size)
{
    (void)in_sizes; (void)n_in; (void)out_size;
    const float* x  = (const float*)d_in[0];
    const float* qw = (const float*)d_in[1];
    const float* kw = (const float*)d_in[2];
    const float* f1 = (const float*)d_in[3];
    const float* f2 = (const float*)d_in[4];

    dim3 pb(64, NH);
    prep_kernel<<<NTOK, pb>>>(x, qw, kw, f1, f2);

    dim3 vg(NTOK / 64, HD / 64, NH);
    vtrans_kernel<<<vg, THREADS>>>(x);

    const int smem = 2 * BUFSZ * (int)sizeof(__nv_bfloat16);  /* 143360 B */
    cudaFuncSetAttribute(attn_kernel, cudaFuncAttributeMaxDynamicSharedMemorySize, smem);
    dim3 ag(NTOK / BR, NH);
    attn_kernel<<<ag, THREADS, smem>>>((float*)d_out);
}

// round 6
// speedup vs baseline: 3.2472x; 1.0813x over previous
#include <cuda_runtime.h>
#include <cuda_bf16.h>
#include <math.h>

#define NTOK 4096
#define NH   16
#define HD   128
#define TXT  3072
/* SCALE * log2(e): logits computed directly in log2 domain */
#define QSCALE 0.12752792696929322f

#define BR 64
#define BC 64
#define KST 136                 /* K smem row stride (bf16): 68 words == 4 mod 32 */
#define VST 72                  /* V^T smem row stride (bf16): 36 words == 4 mod 32 */
#define TILE_K (BC * KST)       /* 8704 elems */
#define TILE_V (HD * VST)       /* 9216 elems */
#define BUFSZ  (2 * TILE_K + 2 * TILE_V)   /* 35840 elems = 71680 bytes */
#define THREADS 128
#define PTHREADS 256
#define NKT (NTOK / BC)         /* 64 */

typedef unsigned int u32;

/* split-bf16 scratch. Q/K: [h][n][d].  V: transposed [h][d][n]. */
__device__ __nv_bfloat16 Qhi_g[NH * NTOK * HD];
__device__ __nv_bfloat16 Qlo_g[NH * NTOK * HD];
__device__ __nv_bfloat16 Khi_g[NH * NTOK * HD];
__device__ __nv_bfloat16 Klo_g[NH * NTOK * HD];
__device__ __nv_bfloat16 VhiT_g[NH * HD * NTOK];
__device__ __nv_bfloat16 VloT_g[NH * HD * NTOK];

/* pack two f32 -> bf16x2 reg, low 16 bits = 'lo' argument */
__device__ __forceinline__ u32 packbf(float lo, float hi) {
    u32 r; asm("cvt.rn.bf16x2.f32 %0, %1, %2;" : "=r"(r) : "f"(hi), "f"(lo));
    return r;
}
/* residual (x - bf16(x)) pair, packed */
__device__ __forceinline__ u32 residbf(float lo, float hi, u32 hipack) {
    float h0 = __uint_as_float(hipack << 16);
    float h1 = __uint_as_float(hipack & 0xffff0000u);
    return packbf(lo - h0, hi - h1);
}
__device__ __forceinline__ float ex2f(float x) {
    float r; asm("ex2.approx.f32 %0, %1;" : "=f"(r) : "f"(x)); return r;
}

__device__ __forceinline__ void mma_bf16(float* c, const u32* a, u32 b0, u32 b1) {
    asm("mma.sync.aligned.m16n8k16.row.col.f32.bf16.bf16.f32 "
        "{%0,%1,%2,%3}, {%4,%5,%6,%7}, {%8,%9}, {%0,%1,%2,%3};"
        : "+f"(c[0]), "+f"(c[1]), "+f"(c[2]), "+f"(c[3])
        : "r"(a[0]), "r"(a[1]), "r"(a[2]), "r"(a[3]), "r"(b0), "r"(b1));
}

__device__ __forceinline__ void cpa16(u32 saddr, const void* g) {
    asm volatile("cp.async.cg.shared.global [%0], [%1], 16;" :: "r"(saddr), "l"(g) : "memory");
}

/* ------------------------------------------------------------------ */
/* prep: split + rmsnorm(q,k) + rope(q,k) -> split-bf16. Q pre-scaled. */
/* ------------------------------------------------------------------ */
__global__ void prep_kernel(const float* __restrict__ x,
                            const float* __restrict__ qw,
                            const float* __restrict__ kw,
                            const float* __restrict__ f1,
                            const float* __restrict__ f2)
{
    const int n = blockIdx.x;
    const int h = threadIdx.y;
    const int i = threadIdx.x;   /* pair index 0..63 */

    const float* base = x + (size_t)n * (3 * NH * HD) + h * HD + 2 * i;
    float2 q2 = *(const float2*)(base);
    float2 k2 = *(const float2*)(base + NH * HD);

    float sq = q2.x * q2.x + q2.y * q2.y;
    float sk = k2.x * k2.x + k2.y * k2.y;
#pragma unroll
    for (int m = 16; m >= 1; m >>= 1) {
        sq += __shfl_xor_sync(0xffffffffu, sq, m);
        sk += __shfl_xor_sync(0xffffffffu, sk, m);
    }
    __shared__ float red[NH][2][2];
    if ((i & 31) == 0) { red[h][i >> 5][0] = sq; red[h][i >> 5][1] = sk; }
    __syncthreads();
    sq = red[h][0][0] + red[h][1][0];
    sk = red[h][0][1] + red[h][1][1];

    const float rq = rsqrtf(sq * (1.0f / 128.0f) + 1e-5f);
    const float rk = rsqrtf(sk * (1.0f / 128.0f) + 1e-5f);
    float2 wq = *(const float2*)(qw + 2 * i);
    float2 wk = *(const float2*)(kw + 2 * i);
    float qx = q2.x * rq * wq.x, qy = q2.y * rq * wq.y;
    float kx = k2.x * rk * wk.x, ky = k2.y * rk * wk.y;

    float th = (n < TXT) ? f1[n * 64 + i] : f2[(n - TXT) * 64 + i];
    float sn, cs;
    sincosf(th, &sn, &cs);

    float qox = (qx * cs - qy * sn) * QSCALE;
    float qoy = (qx * sn + qy * cs) * QSCALE;
    float kox = kx * cs - ky * sn, koy = kx * sn + ky * cs;

    int w = ((h * NTOK + n) * HD + 2 * i) >> 1;   /* u32 word index */
    u32 qh = packbf(qox, qoy);
    ((u32*)Qhi_g)[w] = qh;
    ((u32*)Qlo_g)[w] = residbf(qox, qoy, qh);
    u32 kh = packbf(kox, koy);
    ((u32*)Khi_g)[w] = kh;
    ((u32*)Klo_g)[w] = residbf(kox, koy, kh);
}

/* ------------------------------------------------------------------ */
/* vtrans: read V slice of x [n][d], split to bf16 hi/lo, write [h][d][n] */
/* ------------------------------------------------------------------ */
__global__ void vtrans_kernel(const float* __restrict__ x)
{
    __shared__ float tl[64][65];
    const int nt = blockIdx.x, dt = blockIdx.y, h = blockIdx.z;
    const int t = threadIdx.x;

    const float* src = x + (size_t)(nt * 64) * (3 * NH * HD)
                         + 2 * NH * HD + h * HD + dt * 64;
#pragma unroll
    for (int u = 0; u < 4; ++u) {
        int idx = t + u * PTHREADS;       /* 64 rows x 16 float4 */
        int r = idx >> 4, c4 = (idx & 15) << 2;
        float4 v = *(const float4*)(src + (size_t)r * (3 * NH * HD) + c4);
        tl[r][c4] = v.x; tl[r][c4 + 1] = v.y; tl[r][c4 + 2] = v.z; tl[r][c4 + 3] = v.w;
    }
    __syncthreads();

    u32* dhi = (u32*)VhiT_g;
    u32* dlo = (u32*)VloT_g;
#pragma unroll
    for (int u = 0; u < 8; ++u) {
        int widx = t + u * PTHREADS;      /* 64 d-rows x 32 words */
        int dr = widx >> 5, nw = widx & 31;
        float v0 = tl[2 * nw][dr], v1 = tl[2 * nw + 1][dr];
        u32 hp = packbf(v0, v1);
        int w = (((h * HD + dt * 64 + dr) * NTOK) >> 1) + nt * 32 + nw;
        dhi[w] = hp;
        dlo[w] = residbf(v0, v1, hp);
    }
}

/* ------------------------------------------------------------------ */
/* flash attention: 4 warps, 2 CTAs/SM, single smem buffer, no-max softmax */
/* ------------------------------------------------------------------ */
extern __shared__ __nv_bfloat16 smbuf[];

__global__ void __launch_bounds__(THREADS, 2)
attn_kernel(float* __restrict__ out)
{
    const int h = blockIdx.y;
    const int qt = blockIdx.x;
    const int t = threadIdx.x;
    const int warp = t >> 5, lane = t & 31;
    const int gid = lane >> 2, ctid = lane & 3;
    const int qbase = qt * BR;
    const int ra = qbase + warp * 16 + gid;   /* row a; row b = ra + 8 */

    u32 smbase = (u32)__cvta_generic_to_shared(smbuf);

    /* preload Q fragments (hi/lo, pre-scaled into log2 domain) */
    u32 qh[8][4], ql[8][4];
    {
        const u32* Qh32 = (const u32*)Qhi_g;
        const u32* Ql32 = (const u32*)Qlo_g;
        int base = (h * NTOK + ra) * HD;
#pragma unroll
        for (int ks = 0; ks < 8; ++ks) {
            int c0 = ks * 16 + ctid * 2;
            qh[ks][0] = Qh32[(base + c0) >> 1];
            qh[ks][1] = Qh32[(base + 8 * HD + c0) >> 1];
            qh[ks][2] = Qh32[(base + c0 + 8) >> 1];
            qh[ks][3] = Qh32[(base + 8 * HD + c0 + 8) >> 1];
            ql[ks][0] = Ql32[(base + c0) >> 1];
            ql[ks][1] = Ql32[(base + 8 * HD + c0) >> 1];
            ql[ks][2] = Ql32[(base + c0 + 8) >> 1];
            ql[ks][3] = Ql32[(base + 8 * HD + c0 + 8) >> 1];
        }
    }

    float o[16][4];
#pragma unroll
    for (int i = 0; i < 16; ++i)
#pragma unroll
        for (int j = 0; j < 4; ++j) o[i][j] = 0.f;
    float l_a = 0.f, l_b = 0.f;

#pragma unroll 1
    for (int kt = 0; kt < NKT; ++kt) {
        __syncthreads();   /* previous tile fully consumed */
        /* load K hi/lo + V^T hi/lo tile (single buffer) */
        {
            int kb = (h * NTOK + kt * BC) * HD;
            int vb = h * HD * NTOK + kt * BC;
#pragma unroll
            for (int u = 0; u < 8; ++u) {
                int c = t + u * THREADS;               /* 0..1023 */
                int rk = c >> 4, ck = c & 15;          /* K: 64 rows x 16 chunks */
                int rv = c >> 3, cv = c & 7;           /* V: 128 rows x 8 chunks */
                int gk = kb + rk * HD + ck * 8;
                int gv = vb + rv * NTOK + cv * 8;
                u32 sk = smbase + (u32)(rk * KST + ck * 8) * 2u;
                u32 sv = smbase + (u32)(rv * VST + cv * 8) * 2u;
                cpa16(sk,                              Khi_g + gk);
                cpa16(sk + TILE_K * 2,                 Klo_g + gk);
                cpa16(sv + 2 * TILE_K * 2,             VhiT_g + gv);
                cpa16(sv + (2 * TILE_K + TILE_V) * 2,  VloT_g + gv);
            }
            asm volatile("cp.async.commit_group;" ::: "memory");
            asm volatile("cp.async.wait_group 0;" ::: "memory");
        }
        __syncthreads();

        const u32* Kh32 = (const u32*)(smbuf);
        const u32* Kl32 = (const u32*)(smbuf + TILE_K);
        const u32* Vh32 = (const u32*)(smbuf + 2 * TILE_K);
        const u32* Vl32 = (const u32*)(smbuf + 2 * TILE_K + TILE_V);

        /* ---- S = Q K^T (3x split-bf16 MMAs), logits in log2 domain ---- */
        float s[8][4];
#pragma unroll
        for (int nt = 0; nt < 8; ++nt)
#pragma unroll
            for (int j = 0; j < 4; ++j) s[nt][j] = 0.f;

#pragma unroll
        for (int ks = 0; ks < 8; ++ks) {
#pragma unroll
            for (int nt = 0; nt < 8; ++nt) {
                int wi = (nt * 8 + gid) * (KST / 2) + ks * 8 + ctid;
                u32 bh0 = Kh32[wi], bh1 = Kh32[wi + 4];
                u32 bl0 = Kl32[wi], bl1 = Kl32[wi + 4];
                mma_bf16(s[nt], qh[ks], bh0, bh1);
                mma_bf16(s[nt], qh[ks], bl0, bl1);
                mma_bf16(s[nt], ql[ks], bh0, bh1);
            }
        }

        /* ---- softmax numerator: p = exp2(s), no max (bounded logits) ---- */
#pragma unroll
        for (int nt = 0; nt < 8; ++nt) {
            s[nt][0] = ex2f(s[nt][0]);
            s[nt][1] = ex2f(s[nt][1]);
            s[nt][2] = ex2f(s[nt][2]);
            s[nt][3] = ex2f(s[nt][3]);
            l_a += s[nt][0] + s[nt][1];
            l_b += s[nt][2] + s[nt][3];
        }

        /* ---- O += P V (3x split-bf16 MMAs, P register-resident) ---- */
#pragma unroll
        for (int kk = 0; kk < 4; ++kk) {
            u32 pah[4], pal[4];
            pah[0] = packbf(s[2 * kk][0], s[2 * kk][1]);
            pal[0] = residbf(s[2 * kk][0], s[2 * kk][1], pah[0]);
            pah[1] = packbf(s[2 * kk][2], s[2 * kk][3]);
            pal[1] = residbf(s[2 * kk][2], s[2 * kk][3], pah[1]);
            pah[2] = packbf(s[2 * kk + 1][0], s[2 * kk + 1][1]);
            pal[2] = residbf(s[2 * kk + 1][0], s[2 * kk + 1][1], pah[2]);
            pah[3] = packbf(s[2 * kk + 1][2], s[2 * kk + 1][3]);
            pal[3] = residbf(s[2 * kk + 1][2], s[2 * kk + 1][3], pah[3]);
#pragma unroll
            for (int nt2 = 0; nt2 < 16; ++nt2) {
                int wi = (nt2 * 8 + gid) * (VST / 2) + kk * 8 + ctid;
                u32 bh0 = Vh32[wi], bh1 = Vh32[wi + 4];
                u32 bl0 = Vl32[wi], bl1 = Vl32[wi + 4];
                mma_bf16(o[nt2], pah, bh0, bh1);
                mma_bf16(o[nt2], pah, bl0, bl1);
                mma_bf16(o[nt2], pal, bh0, bh1);
            }
        }
    }

    /* ---- epilogue: complete row sums across the quad, normalize, store ---- */
    l_a += __shfl_xor_sync(0xffffffffu, l_a, 1);
    l_a += __shfl_xor_sync(0xffffffffu, l_a, 2);
    l_b += __shfl_xor_sync(0xffffffffu, l_b, 1);
    l_b += __shfl_xor_sync(0xffffffffu, l_b, 2);
    float ia = 1.f / l_a, ib = 1.f / l_b;
    float* orow_a = out + (size_t)ra * (NH * HD) + h * HD;
    float* orow_b = orow_a + (size_t)8 * (NH * HD);
#pragma unroll
    for (int nt2 = 0; nt2 < 16; ++nt2) {
        int col = nt2 * 8 + 2 * ctid;
        *(float2*)(orow_a + col) = make_float2(o[nt2][0] * ia, o[nt2][1] * ia);
        *(float2*)(orow_b + col) = make_float2(o[nt2][2] * ib, o[nt2][3] * ib);
    }
}

/* ------------------------------------------------------------------ */
extern "C" void kernel_launch(void* const* d_in, const int* in_sizes, int n_in,
                              void* d_out, int out_size)
{
    (void)in_sizes; (void)n_in; (void)out_size;
    const float* x  = (const float*)d_in[0];
    const float* qw = (const float*)d_in[1];
    const float* kw = (const float*)d_in[2];
    const float* f1 = (const float*)d_in[3];
    const float* f2 = (const float*)d_in[4];

    dim3 pb(64, NH);
    prep_kernel<<<NTOK, pb>>>(x, qw, kw, f1, f2);

    dim3 vg(NTOK / 64, HD / 64, NH);
    vtrans_kernel<<<vg, PTHREADS>>>(x);

    const int smem = BUFSZ * (int)sizeof(__nv_bfloat16);  /* 71680 B */
    cudaFuncSetAttribute(attn_kernel, cudaFuncAttributeMaxDynamicSharedMemorySize, smem);
    dim3 ag(NTOK / BR, NH);
    attn_kernel<<<ag, THREADS, smem>>>((float*)d_out);
}